// round 1
// baseline (speedup 1.0000x reference)
#include <cuda_runtime.h>
#include <math.h>

// Problem dims (fixed)
#define BDIM 2
#define TDIM 2048
#define CDIM 1024
#define NH   16
#define HD   64
#define MROWS (BDIM*TDIM)   // 4096

// ---------------- device scratch (no allocations allowed) ----------------
__device__ float g_q[(size_t)MROWS*CDIM];   // 16 MB  q after rope, (B,T,H,HD) packed as (M,C)
__device__ float g_k[(size_t)MROWS*HD];     // 1 MB   k after rope
__device__ float g_v[(size_t)MROWS*HD];
__device__ float g_att[(size_t)MROWS*CDIM]; // attention output pre-Wo

// =========================================================================
// Generic tiled SGEMM:  C[M,N] = A[M,K] @ B[K,N] + bias[N]
// Requires M%BM==0, N%BN==0, K%BK==0 (true for all our shapes).
// =========================================================================
template<int BM,int BN,int BK,int TM,int TN>
__global__ void __launch_bounds__((BM/TM)*(BN/TN))
sgemm_bias_kernel(const float* __restrict__ A, const float* __restrict__ B,
                  const float* __restrict__ bias, float* __restrict__ C,
                  int M, int N, int K)
{
    constexpr int THREADS = (BM/TM)*(BN/TN);
    __shared__ float As[BK][BM];
    __shared__ float Bs[BK][BN];

    const int tid  = threadIdx.x;
    const int tcol = tid % (BN/TN);
    const int trow = tid / (BN/TN);
    const int rowBase = blockIdx.y * BM;
    const int colBase = blockIdx.x * BN;

    float acc[TM][TN];
#pragma unroll
    for (int i = 0; i < TM; i++)
#pragma unroll
        for (int j = 0; j < TN; j++) acc[i][j] = 0.0f;

    constexpr int A_LOADS = (BM*BK)/(4*THREADS);
    constexpr int B_LOADS = (BK*BN)/(4*THREADS);
    static_assert(A_LOADS >= 1 && B_LOADS >= 1, "tile/threads mismatch");

    for (int k0 = 0; k0 < K; k0 += BK) {
#pragma unroll
        for (int i = 0; i < A_LOADS; i++) {
            int idx = tid + i*THREADS;               // one float4 per idx
            int r  = idx / (BK/4);
            int c4 = (idx % (BK/4))*4;
            float4 v = *(const float4*)&A[(size_t)(rowBase + r)*K + k0 + c4];
            As[c4+0][r] = v.x; As[c4+1][r] = v.y;
            As[c4+2][r] = v.z; As[c4+3][r] = v.w;
        }
#pragma unroll
        for (int i = 0; i < B_LOADS; i++) {
            int idx = tid + i*THREADS;
            int r  = idx / (BN/4);
            int c4 = (idx % (BN/4))*4;
            *(float4*)&Bs[r][c4] = *(const float4*)&B[(size_t)(k0 + r)*N + colBase + c4];
        }
        __syncthreads();

#pragma unroll
        for (int k = 0; k < BK; k++) {
            float rm[TM], rn[TN];
#pragma unroll
            for (int i = 0; i < TM; i += 4) {
                float4 t4 = *(const float4*)&As[k][trow*TM + i];
                rm[i]=t4.x; rm[i+1]=t4.y; rm[i+2]=t4.z; rm[i+3]=t4.w;
            }
#pragma unroll
            for (int j = 0; j < TN; j += 4) {
                float4 t4 = *(const float4*)&Bs[k][tcol*TN + j];
                rn[j]=t4.x; rn[j+1]=t4.y; rn[j+2]=t4.z; rn[j+3]=t4.w;
            }
#pragma unroll
            for (int i = 0; i < TM; i++)
#pragma unroll
                for (int j = 0; j < TN; j++)
                    acc[i][j] += rm[i]*rn[j];
        }
        __syncthreads();
    }

#pragma unroll
    for (int i = 0; i < TM; i++) {
        int r = rowBase + trow*TM + i;
#pragma unroll
        for (int j = 0; j < TN; j += 4) {
            int c = colBase + tcol*TN + j;
            float4 v;
            v.x = acc[i][j+0] + bias[c+0];
            v.y = acc[i][j+1] + bias[c+1];
            v.z = acc[i][j+2] + bias[c+2];
            v.w = acc[i][j+3] + bias[c+3];
            *(float4*)&C[(size_t)r*N + c] = v;
        }
    }
}

// =========================================================================
// RoPE: in-place on q (B,T,H,HD) and k (B,T,1,HD).
// out[d]    = t1*cos + t2*sin   (d < 32)
// out[d+32] = t1*sin - t2*cos
// =========================================================================
__global__ void rope_kernel(float* __restrict__ q, float* __restrict__ k)
{
    const int total = BDIM*TDIM*(NH+1)*(HD/2);
    int idx = blockIdx.x*blockDim.x + threadIdx.x;
    if (idx >= total) return;
    int pr   = idx & 31;            // pair index 0..31
    int rest = idx >> 5;
    int hh   = rest % (NH+1);       // 0..15 -> q head, 16 -> k
    int bt   = rest / (NH+1);       // 0..4095
    int t    = bt & (TDIM-1);

    // inv_freq = 10000^(-pr/32)
    float inv_freq = expf(-(float)pr * (9.2103403719761836f / 32.0f));
    float ang = (float)t * inv_freq;
    float sn, cs;
    sincosf(ang, &sn, &cs);         // accurate version: args up to ~2047 rad

    float* base = (hh < NH) ? (q + (size_t)bt*CDIM + hh*HD)
                            : (k + (size_t)bt*HD);
    float t1 = base[pr];
    float t2 = base[pr + 32];
    base[pr]      = t1*cs + t2*sn;
    base[pr + 32] = t1*sn - t2*cs;
}

// =========================================================================
// Causal MQA flash attention. BQ=BKV=64, HD=64, 256 threads.
// Thread map: tc = tid&15 -> 4 columns (kv for S, head-dim for O),
//             tr = tid>>4 -> 4 rows (query rows). Row groups = half warps,
//             so softmax reductions use 16-lane shuffles + __syncwarp only.
// =========================================================================
#define QSS 68   // Qs row stride (pad: breaks broadcast bank collision)
#define KTS 68   // Kt row stride
#define VSS 64
#define PSS 68
#define ATT_SMEM_FLOATS (64*QSS + 64*KTS + 64*VSS + 64*PSS)
#define ATT_SMEM_BYTES  (ATT_SMEM_FLOATS*4)

__global__ void __launch_bounds__(256)
attn_kernel(const float* __restrict__ gq, const float* __restrict__ gk,
            const float* __restrict__ gv, float* __restrict__ go)
{
    extern __shared__ float sm[];
    float* Qs = sm;                  // [64][QSS]  Qs[r][d] (pre-scaled by 1/8)
    float* Kt = Qs + 64*QSS;         // [64][KTS]  Kt[d][c]  (K transposed)
    float* Vs = Kt + 64*KTS;         // [64][VSS]  Vs[c][d]
    float* Ps = Vs + 64*VSS;         // [64][PSS]  Ps[r][c]

    const int qtile = blockIdx.x;
    const int h     = blockIdx.y;
    const int b     = blockIdx.z;
    const int tid   = threadIdx.x;
    const int tc    = tid & 15;
    const int tr    = tid >> 4;
    const int r0    = tr*4, c0 = tc*4;
    const int qbase = qtile*64;

    // ---- load Q tile (scaled by 1/sqrt(HD) = 0.125) ----
    {
        const float* qp = gq + ((size_t)(b*TDIM + qbase))*CDIM + h*HD;
#pragma unroll
        for (int i = 0; i < 4; i++) {
            int idx = tid + i*256;
            int r = idx >> 4, d4 = (idx & 15) << 2;
            float4 v = *(const float4*)(qp + (size_t)r*CDIM + d4);
            Qs[r*QSS + d4+0] = v.x*0.125f;
            Qs[r*QSS + d4+1] = v.y*0.125f;
            Qs[r*QSS + d4+2] = v.z*0.125f;
            Qs[r*QSS + d4+3] = v.w*0.125f;
        }
    }

    float o[4][4];
    float m_[4], l_[4];
#pragma unroll
    for (int i = 0; i < 4; i++) {
        m_[i] = -1e30f; l_[i] = 0.0f;
#pragma unroll
        for (int j = 0; j < 4; j++) o[i][j] = 0.0f;
    }

    const int ntiles = qtile + 1;     // causal: only tiles <= diagonal
    for (int t = 0; t < ntiles; t++) {
        const int kvbase = t*64;
        __syncthreads();   // previous iteration done with Kt/Vs

        // K tile, transposed store Kt[d][c] (coalesced scalar loads)
        {
            const float* kp = gk + ((size_t)(b*TDIM + kvbase))*HD;
#pragma unroll
            for (int i = 0; i < 16; i++) {
                int idx = tid + i*256;      // 4096 elems
                int d = idx & 63, rk = idx >> 6;
                Kt[d*KTS + rk] = kp[rk*HD + d];
            }
            const float* vp = gv + ((size_t)(b*TDIM + kvbase))*HD;
#pragma unroll
            for (int i = 0; i < 4; i++) {
                int idx = tid + i*256;
                int r = idx >> 4, d4 = (idx & 15) << 2;
                *(float4*)(Vs + r*VSS + d4) = *(const float4*)(vp + (size_t)r*HD + d4);
            }
        }
        __syncthreads();

        // ---- S = Q K^T (4x4 per thread), float4-vectorized over k ----
        float s[4][4];
#pragma unroll
        for (int i = 0; i < 4; i++)
#pragma unroll
            for (int j = 0; j < 4; j++) s[i][j] = 0.0f;

#pragma unroll
        for (int kk = 0; kk < HD; kk += 4) {
            float qa[4][4], ka[4][4];
#pragma unroll
            for (int i = 0; i < 4; i++) {
                float4 t4 = *(const float4*)(Qs + (r0+i)*QSS + kk);
                qa[i][0]=t4.x; qa[i][1]=t4.y; qa[i][2]=t4.z; qa[i][3]=t4.w;
            }
#pragma unroll
            for (int mm = 0; mm < 4; mm++) {
                float4 t4 = *(const float4*)(Kt + (kk+mm)*KTS + c0);
                ka[mm][0]=t4.x; ka[mm][1]=t4.y; ka[mm][2]=t4.z; ka[mm][3]=t4.w;
            }
#pragma unroll
            for (int i = 0; i < 4; i++)
#pragma unroll
                for (int j = 0; j < 4; j++)
                    s[i][j] += qa[i][0]*ka[0][j] + qa[i][1]*ka[1][j]
                             + qa[i][2]*ka[2][j] + qa[i][3]*ka[3][j];
        }

        // causal mask (diagonal tile only)
        if (t == qtile) {
#pragma unroll
            for (int i = 0; i < 4; i++)
#pragma unroll
                for (int j = 0; j < 4; j++)
                    if (c0 + j > r0 + i) s[i][j] = -1e30f;
        }

        // ---- online softmax: 16-lane shuffle reductions per row ----
#pragma unroll
        for (int i = 0; i < 4; i++) {
            float lm = fmaxf(fmaxf(s[i][0], s[i][1]), fmaxf(s[i][2], s[i][3]));
#pragma unroll
            for (int off = 8; off >= 1; off >>= 1)
                lm = fmaxf(lm, __shfl_xor_sync(0xffffffffu, lm, off, 16));
            float mnew = fmaxf(m_[i], lm);
            float alpha = __expf(m_[i] - mnew);

            s[i][0] = __expf(s[i][0] - mnew);
            s[i][1] = __expf(s[i][1] - mnew);
            s[i][2] = __expf(s[i][2] - mnew);
            s[i][3] = __expf(s[i][3] - mnew);
            float ls = s[i][0] + s[i][1] + s[i][2] + s[i][3];
#pragma unroll
            for (int off = 8; off >= 1; off >>= 1)
                ls += __shfl_xor_sync(0xffffffffu, ls, off, 16);

            m_[i] = mnew;
            l_[i] = l_[i]*alpha + ls;
            o[i][0] *= alpha; o[i][1] *= alpha; o[i][2] *= alpha; o[i][3] *= alpha;

            *(float4*)(Ps + (r0+i)*PSS + c0) = make_float4(s[i][0], s[i][1], s[i][2], s[i][3]);
        }
        __syncwarp();   // Ps rows are produced+consumed within the same half-warp group

        // ---- O += P V, float4-vectorized over c ----
#pragma unroll
        for (int cc = 0; cc < 64; cc += 4) {
            float pa[4][4], va[4][4];
#pragma unroll
            for (int i = 0; i < 4; i++) {
                float4 t4 = *(const float4*)(Ps + (r0+i)*PSS + cc);
                pa[i][0]=t4.x; pa[i][1]=t4.y; pa[i][2]=t4.z; pa[i][3]=t4.w;
            }
#pragma unroll
            for (int mm = 0; mm < 4; mm++) {
                float4 t4 = *(const float4*)(Vs + (cc+mm)*VSS + c0);
                va[mm][0]=t4.x; va[mm][1]=t4.y; va[mm][2]=t4.z; va[mm][3]=t4.w;
            }
#pragma unroll
            for (int i = 0; i < 4; i++)
#pragma unroll
                for (int j = 0; j < 4; j++)
                    o[i][j] += pa[i][0]*va[0][j] + pa[i][1]*va[1][j]
                             + pa[i][2]*va[2][j] + pa[i][3]*va[3][j];
        }
        __syncwarp();   // done reading Ps before next-iteration overwrite
    }

    // ---- normalize + store ----
#pragma unroll
    for (int i = 0; i < 4; i++) {
        float inv = 1.0f / l_[i];
        float4 r;
        r.x = o[i][0]*inv; r.y = o[i][1]*inv; r.z = o[i][2]*inv; r.w = o[i][3]*inv;
        *(float4*)(go + ((size_t)(b*TDIM + qbase + r0 + i))*CDIM + h*HD + c0) = r;
    }
}

// =========================================================================
// launch
// =========================================================================
extern "C" void kernel_launch(void* const* d_in, const int* in_sizes, int n_in,
                              void* d_out, int out_size)
{
    const float* x  = (const float*)d_in[0];
    const float* Wq = (const float*)d_in[1];
    const float* bq = (const float*)d_in[2];
    const float* Wk = (const float*)d_in[3];
    const float* bk = (const float*)d_in[4];
    const float* Wv = (const float*)d_in[5];
    const float* bv = (const float*)d_in[6];
    const float* Wo = (const float*)d_in[7];
    const float* bo = (const float*)d_in[8];
    float* out = (float*)d_out;

    float *qp, *kp, *vp, *ap;
    cudaGetSymbolAddress((void**)&qp, g_q);
    cudaGetSymbolAddress((void**)&kp, g_k);
    cudaGetSymbolAddress((void**)&vp, g_v);
    cudaGetSymbolAddress((void**)&ap, g_att);

    // Q = x @ Wq + bq   (4096 x 1024 x 1024)
    sgemm_bias_kernel<128,128,8,8,8><<<dim3(CDIM/128, MROWS/128), 256>>>(
        x, Wq, bq, qp, MROWS, CDIM, CDIM);
    // K = x @ Wk + bk, V = x @ Wv + bv   (4096 x 64 x 1024)
    sgemm_bias_kernel<64,64,16,4,4><<<dim3(HD/64, MROWS/64), 256>>>(
        x, Wk, bk, kp, MROWS, HD, CDIM);
    sgemm_bias_kernel<64,64,16,4,4><<<dim3(HD/64, MROWS/64), 256>>>(
        x, Wv, bv, vp, MROWS, HD, CDIM);

    // RoPE on q and k
    {
        int total = BDIM*TDIM*(NH+1)*(HD/2);
        rope_kernel<<<(total + 255)/256, 256>>>(qp, kp);
    }

    // causal MQA attention
    cudaFuncSetAttribute(attn_kernel, cudaFuncAttributeMaxDynamicSharedMemorySize,
                         ATT_SMEM_BYTES);
    attn_kernel<<<dim3(TDIM/64, NH, BDIM), 256, ATT_SMEM_BYTES>>>(qp, kp, vp, ap);

    // out = att @ Wo + bo
    sgemm_bias_kernel<128,128,8,8,8><<<dim3(CDIM/128, MROWS/128), 256>>>(
        ap, Wo, bo, out, MROWS, CDIM, CDIM);
}